// round 13
// baseline (speedup 1.0000x reference)
#include <cuda_runtime.h>
#include <cuda_bf16.h>
#include <cstdint>

#define N_NODES 100000
#define N_EDGES 3200000
#define F_IN 256
#define CH 16
#define FCN 64

#define SCAN_B 1024
#define SCAN_NB ((N_NODES + SCAN_B - 1) / SCAN_B)   // 98
#define READY_BIT 0x40000000

#define REC_CAP (N_EDGES + 8 * N_NODES)              // padded CSR capacity

// Scratch: __device__ globals (no allocation allowed). Statically zeroed at
// load; kernels restore zero state each call (scan re-zeros hist; scatter
// resets bpub). CSR padding slots are never written -> stay (0,0) forever:
// src_off=0, w=0 contributes nothing (gathers L1-hot row 0).
__device__ __align__(128) float g_h[N_NODES * CH];
__device__ __align__(128) int2  g_rec[REC_CAP];       // (src*64, w_bits), dst-grouped
__device__ int g_hist[N_NODES];                       // zero-init; re-zeroed in k_scan
__device__ int g_ptr[N_NODES + 1];                    // padded-degree prefix
__device__ int g_cursor[N_NODES];
__device__ int g_bpub[SCAN_NB];                       // zero-init; reset in scatter
__device__ int g_idx_is64;                            // published by k_hist

// ---------------------------------------------------------------------------
// log-halving cross-lane reduction of 16 per-channel partials over 32 lanes.
// 16 shfls instead of 80. Channel chan_of_lane(lane) ends on lane (and l^16).
// ---------------------------------------------------------------------------
__device__ __forceinline__ float reduce16(const float* r, int lane) {
    const unsigned FULL = 0xFFFFFFFFu;
    float t[8];
    bool hi = (lane & 1);
#pragma unroll
    for (int j = 0; j < 8; j++) {
        float give = hi ? r[j] : r[j + 8];
        float keep = hi ? r[j + 8] : r[j];
        t[j] = keep + __shfl_xor_sync(FULL, give, 1);
    }
    float u[4];
    hi = (lane & 2);
#pragma unroll
    for (int j = 0; j < 4; j++) {
        float give = hi ? t[j] : t[j + 4];
        float keep = hi ? t[j + 4] : t[j];
        u[j] = keep + __shfl_xor_sync(FULL, give, 2);
    }
    hi = (lane & 4);
    float g0 = hi ? u[0] : u[2];
    float k0 = hi ? u[2] : u[0];
    float v0 = k0 + __shfl_xor_sync(FULL, g0, 4);
    float g1 = hi ? u[1] : u[3];
    float k1 = hi ? u[3] : u[1];
    float v1 = k1 + __shfl_xor_sync(FULL, g1, 4);

    hi = (lane & 8);
    float g2 = hi ? v0 : v1;
    float k2 = hi ? v1 : v0;
    float w = k2 + __shfl_xor_sync(FULL, g2, 8);

    w += __shfl_xor_sync(FULL, w, 16);
    return w;
}

__device__ __forceinline__ int chan_of_lane(int lane) {
    return ((lane & 1) << 3) | ((lane & 2) << 1) | ((lane & 4) >> 1) | ((lane & 8) >> 3);
}

// ---------------------------------------------------------------------------
// Launch 1: histogram (4 edges/thread via int4, independent REDs) + probe.
// ---------------------------------------------------------------------------
__global__ void __launch_bounds__(256) k_hist(const int* __restrict__ ei32, int E) {
    const unsigned FULL = 0xFFFFFFFFu;
    const int gtid = blockIdx.x * blockDim.x + threadIdx.x;
    const int lane = threadIdx.x & 31;

    // Per-warp dtype probe: odd words 1..63 are 0 iff int64 layout.
    int oddw = ei32[2 * lane + 1];
    unsigned nz = __ballot_sync(FULL, oddw != 0);
    const bool is64 = (nz == 0);
    if (gtid == 0) g_idx_is64 = is64 ? 1 : 0;

    int e = gtid * 4;
    if (e >= E) return;
    if (e + 3 < E) {
        int d0, d1, d2, d3;
        if (is64) {
            int4 pa = *(const int4*)(ei32 + (size_t)2 * (E + e));
            int4 pb = *(const int4*)(ei32 + (size_t)2 * (E + e) + 4);
            d0 = pa.x; d1 = pa.z; d2 = pb.x; d3 = pb.z;
        } else {
            int4 p = *(const int4*)(ei32 + (size_t)E + e);
            d0 = p.x; d1 = p.y; d2 = p.z; d3 = p.w;
        }
        atomicAdd(&g_hist[d0], 1);
        atomicAdd(&g_hist[d1], 1);
        atomicAdd(&g_hist[d2], 1);
        atomicAdd(&g_hist[d3], 1);
    } else {
        for (int q = 0; q < 4 && e + q < E; q++) {
            int dst = is64 ? ei32[(size_t)2 * (E + e + q)] : ei32[(size_t)E + e + q];
            atomicAdd(&g_hist[dst], 1);
        }
    }
}

// ---------------------------------------------------------------------------
// Launch 2: single-pass scan (decoupled lookback) over PADDED degrees
// (multiple of 8 -> branch-free k2d). 98 blocks all resident -> spin is
// deadlock-free. Re-zeros g_hist.
// ---------------------------------------------------------------------------
__global__ void k_scan() {
    __shared__ int s[SCAN_B];
    __shared__ int s_off;
    const int t = threadIdx.x;
    const int b = blockIdx.x;
    const int idx = b * SCAN_B + t;

    int v = 0;
    if (idx < N_NODES) {
        int d = g_hist[idx];
        g_hist[idx] = 0;                 // restore zero state for next call
        v = (d + 7) & ~7;                // padded degree
    }
    s[t] = v;
    __syncthreads();
#pragma unroll
    for (int off = 1; off < SCAN_B; off <<= 1) {
        int u = (t >= off) ? s[t - off] : 0;
        __syncthreads();
        s[t] += u;
        __syncthreads();
    }

    if (t == 0) {
        s_off = 0;
        atomicExch(&g_bpub[b], s[SCAN_B - 1] | READY_BIT);   // publish own total
    }
    __syncthreads();

    if (t < b) {
        int u;
        do { u = atomicAdd(&g_bpub[t], 0); } while (!(u & READY_BIT));
        atomicAdd(&s_off, u & ~READY_BIT);
    }
    __syncthreads();

    int p = s[t] - v + s_off;            // global exclusive prefix (padded)
    if (idx < N_NODES) {
        g_ptr[idx] = p;
        g_cursor[idx] = p;
    }
    if (b == SCAN_NB - 1 && t == SCAN_B - 1)
        g_ptr[N_NODES] = s[t] + s_off;
}

// ---------------------------------------------------------------------------
// Launch 3: scatter, 4 edges per thread. int4/float4 coalesced loads, then
// 4 INDEPENDENT atomic+store chains in flight. Resets lookback flags.
// ---------------------------------------------------------------------------
__global__ void __launch_bounds__(256) k_scatter(
        const int* __restrict__ ei32, const float* __restrict__ ew, int E) {
    if (blockIdx.x == 0 && threadIdx.x < SCAN_NB) g_bpub[threadIdx.x] = 0;

    int gtid = blockIdx.x * blockDim.x + threadIdx.x;
    int e = gtid * 4;
    if (e >= E) return;

    int s0, s1, s2, s3, d0, d1, d2, d3;
    if (g_idx_is64) {
        int4 sa = *(const int4*)(ei32 + (size_t)2 * e);
        int4 sb = *(const int4*)(ei32 + (size_t)2 * e + 4);
        int4 da = *(const int4*)(ei32 + (size_t)2 * (E + e));
        int4 db = *(const int4*)(ei32 + (size_t)2 * (E + e) + 4);
        s0 = sa.x; s1 = sa.z; s2 = sb.x; s3 = sb.z;
        d0 = da.x; d1 = da.z; d2 = db.x; d3 = db.z;
    } else {
        int4 sv = *(const int4*)(ei32 + e);
        int4 dv = *(const int4*)(ei32 + (size_t)E + e);
        s0 = sv.x; s1 = sv.y; s2 = sv.z; s3 = sv.w;
        d0 = dv.x; d1 = dv.y; d2 = dv.z; d3 = dv.w;
    }
    float4 wv = *(const float4*)(ew + e);

    int p0 = atomicAdd(&g_cursor[d0], 1);
    int p1 = atomicAdd(&g_cursor[d1], 1);
    int p2 = atomicAdd(&g_cursor[d2], 1);
    int p3 = atomicAdd(&g_cursor[d3], 1);
    g_rec[p0] = make_int2(s0 << 6, __float_as_int(wv.x));
    g_rec[p1] = make_int2(s1 << 6, __float_as_int(wv.y));
    g_rec[p2] = make_int2(s2 << 6, __float_as_int(wv.z));
    g_rec[p3] = make_int2(s3 << 6, __float_as_int(wv.w));
}

// ---------------------------------------------------------------------------
// Launch 4 [PROFILED]: h = x @ w_gcn. 4 nodes/warp, float4 x loads,
// LDS.128 weights. Prologue staging now conflict-free (consecutive threads
// write consecutive smem words).
// ---------------------------------------------------------------------------
__global__ void __launch_bounds__(256) k_gemv(
        const float* __restrict__ x, const float* __restrict__ w_gcn) {
    __shared__ __align__(16) float w_t[F_IN * CH];   // [c][k], pitch 256
    const int tid = threadIdx.x;
    // Conflict-free staging: thread t writes smem word t, t+256, ...
    // smem index i = c*256 + k  ->  gmem index k*16 + c.
    for (int i = tid; i < F_IN * CH; i += 256) {
        int c = i >> 8;
        int k = i & 255;
        w_t[i] = w_gcn[k * CH + c];
    }
    __syncthreads();

    const int gtid = blockIdx.x * blockDim.x + tid;
    const int lane = tid & 31;
    const int warp = gtid >> 5;
    const int n0 = warp * 4;
    if (n0 >= N_NODES) return;       // N_NODES % 4 == 0

    const float4* __restrict__ xr4 = (const float4*)(x + (size_t)n0 * F_IN);
    const float4* wt4 = (const float4*)w_t;          // [c][k4], pitch 64

    float acc0[CH], acc1[CH], acc2[CH], acc3[CH];
#pragma unroll
    for (int c = 0; c < CH; c++) { acc0[c] = acc1[c] = acc2[c] = acc3[c] = 0.f; }

#pragma unroll
    for (int i = 0; i < 2; i++) {
        int k4 = i * 32 + lane;                      // float4 column index
        float4 xa = xr4[k4];                         // LDG.128, coalesced
        float4 xb = xr4[64 + k4];
        float4 xc = xr4[128 + k4];
        float4 xd = xr4[192 + k4];
#pragma unroll
        for (int c = 0; c < CH; c++) {
            float4 wv = wt4[c * 64 + k4];            // LDS.128, conflict-free
            acc0[c] += xa.x * wv.x + xa.y * wv.y + xa.z * wv.z + xa.w * wv.w;
            acc1[c] += xb.x * wv.x + xb.y * wv.y + xb.z * wv.z + xb.w * wv.w;
            acc2[c] += xc.x * wv.x + xc.y * wv.y + xc.z * wv.z + xc.w * wv.w;
            acc3[c] += xd.x * wv.x + xd.y * wv.y + xd.z * wv.z + xd.w * wv.w;
        }
    }

    const int chan = chan_of_lane(lane);
    float s0 = reduce16(acc0, lane);
    float s1 = reduce16(acc1, lane);
    float s2 = reduce16(acc2, lane);
    float s3 = reduce16(acc3, lane);
    if (lane < 16) {
        g_h[(size_t)(n0 + 0) * CH + chan] = s0;
        g_h[(size_t)(n0 + 1) * CH + chan] = s1;
        g_h[(size_t)(n0 + 2) * CH + chan] = s2;
        g_h[(size_t)(n0 + 3) * CH + chan] = s3;
    }
}

// ---------------------------------------------------------------------------
// Launch 5: atomic-free aggregation FUSED with FCN head. One warp per node.
// Software-pipelined: next record LDG issues before the current gather ->
// 2x effective MLP in the L2-latency window. Padded CSR (multiple of 8),
// records hold src*64 (gather address = one IADD).
// ---------------------------------------------------------------------------
__global__ void k2d_agg_head(const float* __restrict__ w0, const float* __restrict__ b0,
                             const float* __restrict__ w1, const float* __restrict__ b1,
                             float* __restrict__ out) {
    __shared__ float s_w0[CH * FCN];    // [c][f]: lane-consecutive reads
    __shared__ float s_w1[FCN];
    __shared__ float s_b0[FCN];
    __shared__ float s_b1;
    const int tid = threadIdx.x;
    for (int i = tid; i < CH * FCN; i += blockDim.x) s_w0[i] = w0[i];
    for (int i = tid; i < FCN; i += blockDim.x) { s_w1[i] = w1[i]; s_b0[i] = b0[i]; }
    if (tid == 0) s_b1 = b1[0];
    __syncthreads();

    const unsigned FULL = 0xFFFFFFFFu;
    int gtid = blockIdx.x * blockDim.x + tid;
    int n = gtid >> 5;
    if (n >= N_NODES) return;
    int lane = tid & 31;
    int slot = lane >> 2;               // 0..7
    const char* hbase = (const char*)g_h + ((lane & 3) << 4);

    int start = g_ptr[n];
    int end = g_ptr[n + 1];             // end-start is a multiple of 8

    float ax = 0.f, ay = 0.f, az = 0.f, aw = 0.f;

    if (start < end) {
        int idx = start + slot;
        int2 r = g_rec[idx];                           // 4 lanes same addr: bcast
#pragma unroll 2
        for (idx += 8; idx < end; idx += 8) {
            int2 rn = g_rec[idx];                      // prefetch next batch
            float w = __int_as_float(r.y);
            const float4 hv = *(const float4*)(hbase + r.x);
            ax += hv.x * w; ay += hv.y * w; az += hv.z * w; aw += hv.w * w;
            r = rn;
        }
        float w = __int_as_float(r.y);
        const float4 hv = *(const float4*)(hbase + r.x);
        ax += hv.x * w; ay += hv.y * w; az += hv.z * w; aw += hv.w * w;
    }

    // Reduce across the 8 edge-slots: lanes 0-3 hold the 16 channels
#pragma unroll
    for (int m = 4; m <= 16; m <<= 1) {
        ax += __shfl_xor_sync(FULL, ax, m);
        ay += __shfl_xor_sync(FULL, ay, m);
        az += __shfl_xor_sync(FULL, az, m);
        aw += __shfl_xor_sync(FULL, aw, m);
    }

    // Broadcast the 16 channels (relu'd) to all lanes
    float a[CH];
#pragma unroll
    for (int q = 0; q < 4; q++) {
        a[4 * q + 0] = fmaxf(__shfl_sync(FULL, ax, q), 0.f);
        a[4 * q + 1] = fmaxf(__shfl_sync(FULL, ay, q), 0.f);
        a[4 * q + 2] = fmaxf(__shfl_sync(FULL, az, q), 0.f);
        a[4 * q + 3] = fmaxf(__shfl_sync(FULL, aw, q), 0.f);
    }

    // FCN head: lane l computes units f=l and f=l+32.
    float o1a = s_b0[lane];
    float o1b = s_b0[lane + 32];
#pragma unroll
    for (int c = 0; c < CH; c++) {
        o1a += a[c] * s_w0[c * FCN + lane];        // conflict-free LDS
        o1b += a[c] * s_w0[c * FCN + lane + 32];
    }
    o1a = fmaxf(o1a, 0.f);
    o1b = fmaxf(o1b, 0.f);
    float o2 = o1a * s_w1[lane] + o1b * s_w1[lane + 32];
#pragma unroll
    for (int m = 16; m > 0; m >>= 1)
        o2 += __shfl_xor_sync(FULL, o2, m);
    if (lane == 0) out[n] = o2 + s_b1;
}

// ---------------------------------------------------------------------------
// Launcher. Inputs identified by element count (robust to ordering):
//   x: 25,600,000   edge_index: 6,400,000   edge_w: 3,200,000
//   w_gcn: 4096     w0: 1024   b0: 64 (first)   w1: 64 (second)   b1: 1
// ---------------------------------------------------------------------------
extern "C" void kernel_launch(void* const* d_in, const int* in_sizes, int n_in,
                              void* d_out, int out_size) {
    const float* x = nullptr;
    const int* ei = nullptr;
    const float* ew = nullptr;
    const float* wg = nullptr;
    const float* w0 = nullptr;
    const float* b0 = nullptr;
    const float* w1 = nullptr;
    const float* b1 = nullptr;
    int E = 0;
    int seen64 = 0;

    for (int i = 0; i < n_in; i++) {
        int s = in_sizes[i];
        if (s == N_NODES * F_IN)      x  = (const float*)d_in[i];
        else if (s == 2 * N_EDGES)    { ei = (const int*)d_in[i]; E = s / 2; }
        else if (s == N_EDGES)        ew = (const float*)d_in[i];
        else if (s == F_IN * CH)      wg = (const float*)d_in[i];
        else if (s == CH * FCN)       w0 = (const float*)d_in[i];
        else if (s == FCN)            { if (seen64++ == 0) b0 = (const float*)d_in[i];
                                        else               w1 = (const float*)d_in[i]; }
        else if (s == 1)              b1 = (const float*)d_in[i];
    }

    float* out = (float*)d_out;

    // Launch 1: histogram + dtype probe (4 edges/thread)
    k_hist<<<(N_EDGES / 4 + 255) / 256, 256>>>(ei, E);

    // Launch 2: single-pass lookback scan (padded degrees)
    k_scan<<<SCAN_NB, SCAN_B>>>();

    // Launch 3: scatter, 4 edges/thread (MLP 4)
    k_scatter<<<(N_EDGES / 4 + 255) / 256, 256>>>(ei, ew, E);

    // Launch 4 [PROFILED]: GEMV, independent of launches 1-3
    {
        int warps = N_NODES / 4;                 // 25000
        int blocks = warps * 32 / 256;           // 3125
        k_gemv<<<blocks, 256>>>(x, wg);
    }

    // Launch 5: atomic-free aggregation + FCN head, warp per node
    k2d_agg_head<<<(N_NODES * 32 + 255) / 256, 256>>>(w0, b0, w1, b1, out);
}

// round 14
// speedup vs baseline: 1.0551x; 1.0551x over previous
#include <cuda_runtime.h>
#include <cuda_bf16.h>
#include <cstdint>

#define N_NODES 100000
#define N_EDGES 3200000
#define F_IN 256
#define CH 16
#define FCN 64

#define SCAN_B 1024
#define SCAN_NB ((N_NODES + SCAN_B - 1) / SCAN_B)   // 98
#define READY_BIT 0x40000000

#define REC_CAP (N_EDGES + 8 * N_NODES)              // padded CSR capacity

// Scratch: __device__ globals (no allocation allowed). Statically zeroed at
// load; kernels restore zero state each call (scan re-zeros hist; scatter
// resets bpub). CSR padding slots are never written -> stay (0,0) forever:
// src_off=0, w=0 contributes nothing (gathers L1-hot row 0).
__device__ __align__(128) float g_h[N_NODES * CH];
__device__ __align__(128) int2  g_rec[REC_CAP];       // (src*64, w_bits), dst-grouped
__device__ int g_hist[N_NODES];                       // zero-init; re-zeroed in k_scan
__device__ int g_ptr[N_NODES + 1];                    // padded-degree prefix
__device__ int g_cursor[N_NODES];
__device__ int g_bpub[SCAN_NB];                       // zero-init; reset in scatter
__device__ int g_idx_is64;                            // published by k1

// ---------------------------------------------------------------------------
// log-halving reduction of 8 per-channel partials over 32 lanes (9 shfls).
// Lane ends holding channel chan8(lane) = bitrev3(lane&7).
// ---------------------------------------------------------------------------
__device__ __forceinline__ float reduce8(const float* r, int lane) {
    const unsigned FULL = 0xFFFFFFFFu;
    float t[4];
    bool hi = (lane & 1);
#pragma unroll
    for (int j = 0; j < 4; j++) {
        float give = hi ? r[j] : r[j + 4];
        float keep = hi ? r[j + 4] : r[j];
        t[j] = keep + __shfl_xor_sync(FULL, give, 1);
    }
    float u[2];
    hi = (lane & 2);
#pragma unroll
    for (int j = 0; j < 2; j++) {
        float give = hi ? t[j] : t[j + 2];
        float keep = hi ? t[j + 2] : t[j];
        u[j] = keep + __shfl_xor_sync(FULL, give, 2);
    }
    hi = (lane & 4);
    float give = hi ? u[0] : u[1];
    float keep = hi ? u[1] : u[0];
    float v = keep + __shfl_xor_sync(FULL, give, 4);
    v += __shfl_xor_sync(FULL, v, 8);
    v += __shfl_xor_sync(FULL, v, 16);
    return v;
}

__device__ __forceinline__ int chan8_of_lane(int lane) {
    return ((lane & 1) << 2) | (lane & 2) | ((lane & 4) >> 2);
}

// ---------------------------------------------------------------------------
// Launch 1: h = x @ w_gcn FUSED with dst histogram + dtype probe.
// 4 nodes/warp; x loaded ONCE into 8 float4 regs; channels processed in
// TWO passes of 8 (accumulators 32 regs instead of 64) -> ~80 regs,
// 3 blocks/SM (occ ~50%) to hide DRAM latency. LDS/FFMA totals unchanged.
// ---------------------------------------------------------------------------
__global__ void __launch_bounds__(256, 3) k1_xw_hist(
        const float* __restrict__ x, const float* __restrict__ w_gcn,
        const int* __restrict__ ei32, int E) {
    const unsigned FULL = 0xFFFFFFFFu;
    __shared__ __align__(16) float w_t[F_IN * CH];   // [c][k], pitch 256
    const int tid = threadIdx.x;
    // Conflict-free staging: thread t writes smem words t, t+256, ...
    for (int i = tid; i < F_IN * CH; i += 256) {
        int c = i >> 8;
        int k = i & 255;
        w_t[i] = w_gcn[k * CH + c];
    }
    __syncthreads();

    const int gtid = blockIdx.x * blockDim.x + tid;
    const int lane = tid & 31;

    // Per-warp dtype probe: odd words 1..63 are 0 iff int64 layout.
    int oddw = ei32[2 * lane + 1];
    unsigned nz = __ballot_sync(FULL, oddw != 0);
    const bool is64 = (nz == 0);
    if (gtid == 0) g_idx_is64 = is64 ? 1 : 0;

    // Histogram: 4 edges/thread (800K threads cover E); REDs hide under x read.
    {
        int e = gtid * 4;
        if (e + 3 < E) {
            int d0, d1, d2, d3;
            if (is64) {
                int4 pa = *(const int4*)(ei32 + (size_t)2 * (E + e));
                int4 pb = *(const int4*)(ei32 + (size_t)2 * (E + e) + 4);
                d0 = pa.x; d1 = pa.z; d2 = pb.x; d3 = pb.z;
            } else {
                int4 p = *(const int4*)(ei32 + (size_t)E + e);
                d0 = p.x; d1 = p.y; d2 = p.z; d3 = p.w;
            }
            atomicAdd(&g_hist[d0], 1);
            atomicAdd(&g_hist[d1], 1);
            atomicAdd(&g_hist[d2], 1);
            atomicAdd(&g_hist[d3], 1);
        } else {
            for (int q = 0; q < 4 && e + q < E; q++) {
                int dst = is64 ? ei32[(size_t)2 * (E + e + q)]
                               : ei32[(size_t)E + e + q];
                atomicAdd(&g_hist[dst], 1);
            }
        }
    }

    const int warp = gtid >> 5;
    const int n0 = warp * 4;
    if (n0 >= N_NODES) return;       // N_NODES % 4 == 0

    const float4* __restrict__ xr4 = (const float4*)(x + (size_t)n0 * F_IN);
    const float4* wt4 = (const float4*)w_t;          // [c][k4], pitch 64

    // Load ALL x once: 8 float4 (32 regs), coalesced LDG.128, MLP 8.
    float4 xa0 = xr4[lane],       xa1 = xr4[32 + lane];
    float4 xb0 = xr4[64 + lane],  xb1 = xr4[96 + lane];
    float4 xc0 = xr4[128 + lane], xc1 = xr4[160 + lane];
    float4 xd0 = xr4[192 + lane], xd1 = xr4[224 + lane];

    const int chan8 = chan8_of_lane(lane);

#pragma unroll
    for (int p = 0; p < 2; p++) {
        float acc0[8], acc1[8], acc2[8], acc3[8];
#pragma unroll
        for (int j = 0; j < 8; j++) { acc0[j] = acc1[j] = acc2[j] = acc3[j] = 0.f; }

#pragma unroll
        for (int j = 0; j < 8; j++) {
            int c = p * 8 + j;
            float4 w0v = wt4[c * 64 + lane];          // LDS.128, conflict-free
            float4 w1v = wt4[c * 64 + 32 + lane];
            acc0[j] += xa0.x * w0v.x + xa0.y * w0v.y + xa0.z * w0v.z + xa0.w * w0v.w
                     + xa1.x * w1v.x + xa1.y * w1v.y + xa1.z * w1v.z + xa1.w * w1v.w;
            acc1[j] += xb0.x * w0v.x + xb0.y * w0v.y + xb0.z * w0v.z + xb0.w * w0v.w
                     + xb1.x * w1v.x + xb1.y * w1v.y + xb1.z * w1v.z + xb1.w * w1v.w;
            acc2[j] += xc0.x * w0v.x + xc0.y * w0v.y + xc0.z * w0v.z + xc0.w * w0v.w
                     + xc1.x * w1v.x + xc1.y * w1v.y + xc1.z * w1v.z + xc1.w * w1v.w;
            acc3[j] += xd0.x * w0v.x + xd0.y * w0v.y + xd0.z * w0v.z + xd0.w * w0v.w
                     + xd1.x * w1v.x + xd1.y * w1v.y + xd1.z * w1v.z + xd1.w * w1v.w;
        }

        float s0 = reduce8(acc0, lane);
        float s1 = reduce8(acc1, lane);
        float s2 = reduce8(acc2, lane);
        float s3 = reduce8(acc3, lane);
        if (lane < 8) {
            int co = p * 8 + chan8;
            g_h[(size_t)(n0 + 0) * CH + co] = s0;
            g_h[(size_t)(n0 + 1) * CH + co] = s1;
            g_h[(size_t)(n0 + 2) * CH + co] = s2;
            g_h[(size_t)(n0 + 3) * CH + co] = s3;
        }
    }
}

// ---------------------------------------------------------------------------
// Launch 2: single-pass scan (decoupled lookback) over PADDED degrees
// (multiple of 8 -> branch-free k2d). 98 blocks all resident -> spin is
// deadlock-free. Re-zeros g_hist.
// ---------------------------------------------------------------------------
__global__ void k_scan() {
    __shared__ int s[SCAN_B];
    __shared__ int s_off;
    const int t = threadIdx.x;
    const int b = blockIdx.x;
    const int idx = b * SCAN_B + t;

    int v = 0;
    if (idx < N_NODES) {
        int d = g_hist[idx];
        g_hist[idx] = 0;                 // restore zero state for next call
        v = (d + 7) & ~7;                // padded degree
    }
    s[t] = v;
    __syncthreads();
#pragma unroll
    for (int off = 1; off < SCAN_B; off <<= 1) {
        int u = (t >= off) ? s[t - off] : 0;
        __syncthreads();
        s[t] += u;
        __syncthreads();
    }

    if (t == 0) {
        s_off = 0;
        atomicExch(&g_bpub[b], s[SCAN_B - 1] | READY_BIT);   // publish own total
    }
    __syncthreads();

    if (t < b) {
        int u;
        do { u = atomicAdd(&g_bpub[t], 0); } while (!(u & READY_BIT));
        atomicAdd(&s_off, u & ~READY_BIT);
    }
    __syncthreads();

    int p = s[t] - v + s_off;            // global exclusive prefix (padded)
    if (idx < N_NODES) {
        g_ptr[idx] = p;
        g_cursor[idx] = p;
    }
    if (b == SCAN_NB - 1 && t == SCAN_B - 1)
        g_ptr[N_NODES] = s[t] + s_off;
}

// ---------------------------------------------------------------------------
// Launch 3: scatter, 4 edges per thread. int4/float4 coalesced loads, then
// 4 INDEPENDENT atomic+store chains in flight. Resets lookback flags.
// ---------------------------------------------------------------------------
__global__ void __launch_bounds__(256) k_scatter(
        const int* __restrict__ ei32, const float* __restrict__ ew, int E) {
    if (blockIdx.x == 0 && threadIdx.x < SCAN_NB) g_bpub[threadIdx.x] = 0;

    int gtid = blockIdx.x * blockDim.x + threadIdx.x;
    int e = gtid * 4;
    if (e >= E) return;

    int s0, s1, s2, s3, d0, d1, d2, d3;
    if (g_idx_is64) {
        int4 sa = *(const int4*)(ei32 + (size_t)2 * e);
        int4 sb = *(const int4*)(ei32 + (size_t)2 * e + 4);
        int4 da = *(const int4*)(ei32 + (size_t)2 * (E + e));
        int4 db = *(const int4*)(ei32 + (size_t)2 * (E + e) + 4);
        s0 = sa.x; s1 = sa.z; s2 = sb.x; s3 = sb.z;
        d0 = da.x; d1 = da.z; d2 = db.x; d3 = db.z;
    } else {
        int4 sv = *(const int4*)(ei32 + e);
        int4 dv = *(const int4*)(ei32 + (size_t)E + e);
        s0 = sv.x; s1 = sv.y; s2 = sv.z; s3 = sv.w;
        d0 = dv.x; d1 = dv.y; d2 = dv.z; d3 = dv.w;
    }
    float4 wv = *(const float4*)(ew + e);

    int p0 = atomicAdd(&g_cursor[d0], 1);
    int p1 = atomicAdd(&g_cursor[d1], 1);
    int p2 = atomicAdd(&g_cursor[d2], 1);
    int p3 = atomicAdd(&g_cursor[d3], 1);
    g_rec[p0] = make_int2(s0 << 6, __float_as_int(wv.x));
    g_rec[p1] = make_int2(s1 << 6, __float_as_int(wv.y));
    g_rec[p2] = make_int2(s2 << 6, __float_as_int(wv.z));
    g_rec[p3] = make_int2(s3 << 6, __float_as_int(wv.w));
}

// ---------------------------------------------------------------------------
// Launch 4 [PROFILED]: atomic-free aggregation FUSED with FCN head.
// One warp per node; software-pipelined record prefetch (2x MLP in the
// L2-gather window). Padded CSR -> branch-free; records hold src*64.
// ---------------------------------------------------------------------------
__global__ void k2d_agg_head(const float* __restrict__ w0, const float* __restrict__ b0,
                             const float* __restrict__ w1, const float* __restrict__ b1,
                             float* __restrict__ out) {
    __shared__ float s_w0[CH * FCN];    // [c][f]: lane-consecutive reads
    __shared__ float s_w1[FCN];
    __shared__ float s_b0[FCN];
    __shared__ float s_b1;
    const int tid = threadIdx.x;
    for (int i = tid; i < CH * FCN; i += blockDim.x) s_w0[i] = w0[i];
    for (int i = tid; i < FCN; i += blockDim.x) { s_w1[i] = w1[i]; s_b0[i] = b0[i]; }
    if (tid == 0) s_b1 = b1[0];
    __syncthreads();

    const unsigned FULL = 0xFFFFFFFFu;
    int gtid = blockIdx.x * blockDim.x + tid;
    int n = gtid >> 5;
    if (n >= N_NODES) return;
    int lane = tid & 31;
    int slot = lane >> 2;               // 0..7
    const char* hbase = (const char*)g_h + ((lane & 3) << 4);

    int start = g_ptr[n];
    int end = g_ptr[n + 1];             // end-start is a multiple of 8

    float ax = 0.f, ay = 0.f, az = 0.f, aw = 0.f;

    if (start < end) {
        int idx = start + slot;
        int2 r = g_rec[idx];                           // 4 lanes same addr: bcast
#pragma unroll 2
        for (idx += 8; idx < end; idx += 8) {
            int2 rn = g_rec[idx];                      // prefetch next batch
            float w = __int_as_float(r.y);
            const float4 hv = *(const float4*)(hbase + r.x);
            ax += hv.x * w; ay += hv.y * w; az += hv.z * w; aw += hv.w * w;
            r = rn;
        }
        float w = __int_as_float(r.y);
        const float4 hv = *(const float4*)(hbase + r.x);
        ax += hv.x * w; ay += hv.y * w; az += hv.z * w; aw += hv.w * w;
    }

    // Reduce across the 8 edge-slots: lanes 0-3 hold the 16 channels
#pragma unroll
    for (int m = 4; m <= 16; m <<= 1) {
        ax += __shfl_xor_sync(FULL, ax, m);
        ay += __shfl_xor_sync(FULL, ay, m);
        az += __shfl_xor_sync(FULL, az, m);
        aw += __shfl_xor_sync(FULL, aw, m);
    }

    // Broadcast the 16 channels (relu'd) to all lanes
    float a[CH];
#pragma unroll
    for (int q = 0; q < 4; q++) {
        a[4 * q + 0] = fmaxf(__shfl_sync(FULL, ax, q), 0.f);
        a[4 * q + 1] = fmaxf(__shfl_sync(FULL, ay, q), 0.f);
        a[4 * q + 2] = fmaxf(__shfl_sync(FULL, az, q), 0.f);
        a[4 * q + 3] = fmaxf(__shfl_sync(FULL, aw, q), 0.f);
    }

    // FCN head: lane l computes units f=l and f=l+32.
    float o1a = s_b0[lane];
    float o1b = s_b0[lane + 32];
#pragma unroll
    for (int c = 0; c < CH; c++) {
        o1a += a[c] * s_w0[c * FCN + lane];        // conflict-free LDS
        o1b += a[c] * s_w0[c * FCN + lane + 32];
    }
    o1a = fmaxf(o1a, 0.f);
    o1b = fmaxf(o1b, 0.f);
    float o2 = o1a * s_w1[lane] + o1b * s_w1[lane + 32];
#pragma unroll
    for (int m = 16; m > 0; m >>= 1)
        o2 += __shfl_xor_sync(FULL, o2, m);
    if (lane == 0) out[n] = o2 + s_b1;
}

// ---------------------------------------------------------------------------
// Launcher. Inputs identified by element count (robust to ordering):
//   x: 25,600,000   edge_index: 6,400,000   edge_w: 3,200,000
//   w_gcn: 4096     w0: 1024   b0: 64 (first)   w1: 64 (second)   b1: 1
// ---------------------------------------------------------------------------
extern "C" void kernel_launch(void* const* d_in, const int* in_sizes, int n_in,
                              void* d_out, int out_size) {
    const float* x = nullptr;
    const int* ei = nullptr;
    const float* ew = nullptr;
    const float* wg = nullptr;
    const float* w0 = nullptr;
    const float* b0 = nullptr;
    const float* w1 = nullptr;
    const float* b1 = nullptr;
    int E = 0;
    int seen64 = 0;

    for (int i = 0; i < n_in; i++) {
        int s = in_sizes[i];
        if (s == N_NODES * F_IN)      x  = (const float*)d_in[i];
        else if (s == 2 * N_EDGES)    { ei = (const int*)d_in[i]; E = s / 2; }
        else if (s == N_EDGES)        ew = (const float*)d_in[i];
        else if (s == F_IN * CH)      wg = (const float*)d_in[i];
        else if (s == CH * FCN)       w0 = (const float*)d_in[i];
        else if (s == FCN)            { if (seen64++ == 0) b0 = (const float*)d_in[i];
                                        else               w1 = (const float*)d_in[i]; }
        else if (s == 1)              b1 = (const float*)d_in[i];
    }

    float* out = (float*)d_out;

    // Launch 1: GEMV (4 nodes/warp, 2-pass channels, occ-tuned) + hist + probe
    {
        int warps = N_NODES / 4;                 // 25000 -> 800K threads = E/4
        int blocks = warps * 32 / 256;           // 3125
        k1_xw_hist<<<blocks, 256>>>(x, wg, ei, E);
    }

    // Launch 2: single-pass lookback scan (padded degrees)
    k_scan<<<SCAN_NB, SCAN_B>>>();

    // Launch 3: scatter, 4 edges/thread (MLP 4)
    k_scatter<<<(N_EDGES / 4 + 255) / 256, 256>>>(ei, ew, E);

    // Launch 4 [PROFILED]: aggregation + FCN head (verify prefetch delta)
    k2d_agg_head<<<(N_NODES * 32 + 255) / 256, 256>>>(w0, b0, w1, b1, out);
}